// round 4
// baseline (speedup 1.0000x reference)
#include <cuda_runtime.h>
#include <cuda_fp16.h>

// ---------------------------------------------------------------------------
// ViSNeRF fused sampler, round 4 (round-3 theory, dynamic smem fix):
//   - fp16 channel-last planes (global gather, 24 LDG.128/point)
//   - fp16 line table staged in dynamic SHARED MEMORY (48KB) -> LDS path
//   - 512-thread blocks, grid-stride tile loop to amortize staging
// ---------------------------------------------------------------------------

#define RES    512
#define NCOMP  16
#define NOUT   32
#define NIN    19
#define TPB    512

#define N_LINE_VECS (3 * RES * 2)          // 3072 uint4 = 48KB
// dynamic smem layout (in bytes):
//   [0,                48KB+32)   s_lines  (uint4[3072+2])
//   [next, +TPB*3*4)              s_pts
//   [next, +TPB*4)                s_ts
//   [next, +NOUT*NIN*4)           sW
#define SMEM_LINES_BYTES ((N_LINE_VECS + 2) * 16)
#define SMEM_PTS_BYTES   (TPB * 3 * 4)
#define SMEM_TS_BYTES    (TPB * 4)
#define SMEM_W_BYTES     (NOUT * NIN * 4)
#define SMEM_TOTAL (SMEM_LINES_BYTES + SMEM_PTS_BYTES + SMEM_TS_BYTES + SMEM_W_BYTES)

// One pixel = 16 halfs = 32 B = 2 uint4.
static __device__ uint4 g_planeH[3 * RES * RES * 2 + 4];
static __device__ uint4 g_lineH[3 * RES * 2 + 4];

// ---- transpose+quantize planes [p][c][y][x] fp32 -> [p][y][x][c] fp16 ------
__global__ void k_transpose_planes(const float* __restrict__ planes) {
    int t = blockIdx.x * blockDim.x + threadIdx.x;
    const int HW = RES * RES;
    if (t >= 3 * HW) return;
    int p  = t / HW;
    int yx = t - p * HW;
    __half2 h[8];
#pragma unroll
    for (int k = 0; k < 8; ++k) {
        float a = planes[(size_t)(p * NCOMP + 2 * k)     * HW + yx];
        float b = planes[(size_t)(p * NCOMP + 2 * k + 1) * HW + yx];
        h[k] = __floats2half2_rn(a, b);
    }
    uint4* dst = g_planeH + (size_t)t * 2;
    dst[0] = *reinterpret_cast<uint4*>(&h[0]);
    dst[1] = *reinterpret_cast<uint4*>(&h[4]);
}

// ---- transpose+quantize lines [p][c][y] -> [p][y][c] fp16 -------------------
__global__ void k_transpose_lines(const float* __restrict__ lines) {
    int t = blockIdx.x * blockDim.x + threadIdx.x;
    if (t >= 3 * RES) return;
    int p = t / RES;
    int y = t - p * RES;
    __half2 h[8];
#pragma unroll
    for (int k = 0; k < 8; ++k) {
        float a = lines[(p * NCOMP + 2 * k)     * RES + y];
        float b = lines[(p * NCOMP + 2 * k + 1) * RES + y];
        h[k] = __floats2half2_rn(a, b);
    }
    uint4* dst = g_lineH + (size_t)t * 2;
    dst[0] = *reinterpret_cast<uint4*>(&h[0]);
    dst[1] = *reinterpret_cast<uint4*>(&h[4]);
}

// ---- main fused kernel ------------------------------------------------------
__global__ void __launch_bounds__(TPB) k_visnerf(
    const float* __restrict__ pts,      // [N,3]
    const float* __restrict__ ts,       // [N,1]
    const float* __restrict__ params,   // [3,3]
    const float* __restrict__ W,        // [32,19]
    float*       __restrict__ out,      // [N,32]
    int n)
{
    extern __shared__ char smem_raw[];
    uint4* s_lines = reinterpret_cast<uint4*>(smem_raw);
    float* s_pts   = reinterpret_cast<float*>(smem_raw + SMEM_LINES_BYTES);
    float* s_ts    = reinterpret_cast<float*>(smem_raw + SMEM_LINES_BYTES + SMEM_PTS_BYTES);
    float* sW      = reinterpret_cast<float*>(smem_raw + SMEM_LINES_BYTES + SMEM_PTS_BYTES + SMEM_TS_BYTES);

    // stage weights + line table (once per block)
    for (int i = threadIdx.x; i < NOUT * NIN; i += TPB) sW[i] = W[i];
#pragma unroll
    for (int j = 0; j < N_LINE_VECS / TPB; ++j)
        s_lines[j * TPB + threadIdx.x] = g_lineH[j * TPB + threadIdx.x];
    if (threadIdx.x < 2)
        s_lines[N_LINE_VECS + threadIdx.x] = g_lineH[N_LINE_VECS + threadIdx.x];

    const float B  = 1.3f;
    const float sc = 2.0f / (-2.0f * B);
    const int MX[3] = {0, 0, 1};
    const int MY[3] = {1, 2, 2};
    const int VM[3] = {2, 1, 0};

    int ntiles = (n + TPB - 1) / TPB;
    for (int tile = blockIdx.x; tile < ntiles; tile += gridDim.x) {
        int base = tile * TPB;
        __syncthreads();   // protect s_pts/s_ts from previous iteration readers

        if (base + TPB <= n) {
            const float4* gp = reinterpret_cast<const float4*>(pts + (size_t)base * 3);
            if (threadIdx.x < (TPB * 3) / 4)
                reinterpret_cast<float4*>(s_pts)[threadIdx.x] = gp[threadIdx.x];
            const float4* gt = reinterpret_cast<const float4*>(ts + base);
            if (threadIdx.x < TPB / 4)
                reinterpret_cast<float4*>(s_ts)[threadIdx.x] = gt[threadIdx.x];
        } else {
            int i = base + threadIdx.x;
            if (i < n) {
                s_pts[threadIdx.x * 3 + 0] = pts[(size_t)i * 3 + 0];
                s_pts[threadIdx.x * 3 + 1] = pts[(size_t)i * 3 + 1];
                s_pts[threadIdx.x * 3 + 2] = pts[(size_t)i * 3 + 2];
                s_ts[threadIdx.x] = ts[i];
            }
        }
        __syncthreads();

        int i = base + threadIdx.x;
        if (i >= n) continue;

        float pn[3];
#pragma unroll
        for (int d = 0; d < 3; ++d)
            pn[d] = (s_pts[threadIdx.x * 3 + d] - B) * sc - 1.0f;

        float2 coef[8];
#pragma unroll
        for (int k = 0; k < 8; ++k) coef[k] = make_float2(0.f, 0.f);

#pragma unroll
        for (int p = 0; p < 3; ++p) {
            float gx = pn[MX[p]];
            float gy = pn[MY[p]];
            float lc = pn[VM[p]];

            float ix = (gx + 1.0f) * 0.5f * (float)(RES - 1);
            float iy = (gy + 1.0f) * 0.5f * (float)(RES - 1);
            float fx = floorf(ix), fy = floorf(iy);
            float wx = ix - fx,   wy = iy - fy;
            int x0 = min(max((int)fx, 0), RES - 1);
            int y0 = min(max((int)fy, 0), RES - 1);
            int y1 = min(y0 + 1, RES - 1);
            float w00 = (1.0f - wy) * (1.0f - wx);
            float w01 = (1.0f - wy) * wx;
            float w10 = wy * (1.0f - wx);
            float w11 = wy * wx;

            // pair-load: pixels (x0, x0+1) are 64B contiguous
            const uint4* r0 = g_planeH + (size_t)((p * RES + y0) * RES + x0) * 2;
            const uint4* r1 = g_planeH + (size_t)((p * RES + y1) * RES + x0) * 2;
            uint4 rowA[4] = { r0[0], r0[1], r0[2], r0[3] };
            uint4 rowB[4] = { r1[0], r1[1], r1[2], r1[3] };

            // line sample from SMEM: pixels (l0, l0+1) are 64B contiguous
            float il = (lc + 1.0f) * 0.5f * (float)(RES - 1);
            float fl = floorf(il);
            float wl = il - fl;
            int l0 = min(max((int)fl, 0), RES - 1);
            const uint4* lr = s_lines + (size_t)(p * RES + l0) * 2;
            uint4 rowL[4] = { lr[0], lr[1], lr[2], lr[3] };

            const __half2* h00 = reinterpret_cast<const __half2*>(&rowA[0]);
            const __half2* h01 = reinterpret_cast<const __half2*>(&rowA[2]);
            const __half2* h10 = reinterpret_cast<const __half2*>(&rowB[0]);
            const __half2* h11 = reinterpret_cast<const __half2*>(&rowB[2]);
            const __half2* hl0 = reinterpret_cast<const __half2*>(&rowL[0]);
            const __half2* hl1 = reinterpret_cast<const __half2*>(&rowL[2]);

            float omwl = 1.0f - wl;

#pragma unroll
            for (int k = 0; k < 8; ++k) {
                float2 f00 = __half22float2(h00[k]);
                float2 f01 = __half22float2(h01[k]);
                float2 f10 = __half22float2(h10[k]);
                float2 f11 = __half22float2(h11[k]);
                float px = fmaf(f00.x, w00, fmaf(f01.x, w01, fmaf(f10.x, w10, f11.x * w11)));
                float py = fmaf(f00.y, w00, fmaf(f01.y, w01, fmaf(f10.y, w10, f11.y * w11)));

                float2 g0 = __half22float2(hl0[k]);
                float2 g1 = __half22float2(hl1[k]);
                float lx = fmaf(g0.x, omwl, g1.x * wl);
                float ly = fmaf(g0.y, omwl, g1.y * wl);

                coef[k].x = fmaf(px, lx, coef[k].x);
                coef[k].y = fmaf(py, ly, coef[k].y);
            }
        }

        // pfeat = _sample1d(params_grid [3,3], t)
        float t  = s_ts[threadIdx.x];
        float it = (t + 1.0f) * 0.5f * 2.0f;
        float ft = floorf(it);
        float wt = it - ft;
        int a0 = min(max((int)ft, 0), 2);
        int a1 = min(a0 + 1, 2);
        float pf[3];
#pragma unroll
        for (int j = 0; j < 3; ++j)
            pf[j] = fmaf(__ldg(&params[j * 3 + a0]), 1.0f - wt,
                         __ldg(&params[j * 3 + a1]) * wt);

        float cf[NCOMP];
#pragma unroll
        for (int k = 0; k < 8; ++k) {
            cf[2 * k + 0] = coef[k].x;
            cf[2 * k + 1] = coef[k].y;
        }

        float* op = out + (size_t)i * NOUT;
#pragma unroll
        for (int o4 = 0; o4 < NOUT / 4; ++o4) {
            float4 r;
            float* rr = reinterpret_cast<float*>(&r);
#pragma unroll
            for (int kk = 0; kk < 4; ++kk) {
                int o = o4 * 4 + kk;
                float acc = 0.0f;
#pragma unroll
                for (int c = 0; c < NCOMP; ++c)
                    acc = fmaf(cf[c], sW[o * NIN + c], acc);
#pragma unroll
                for (int j = 0; j < 3; ++j)
                    acc = fmaf(pf[j], sW[o * NIN + NCOMP + j], acc);
                rr[kk] = acc;
            }
            reinterpret_cast<float4*>(op)[o4] = r;
        }
    }
}

// ---------------------------------------------------------------------------
extern "C" void kernel_launch(void* const* d_in, const int* in_sizes, int n_in,
                              void* d_out, int out_size) {
    const float* pts    = (const float*)d_in[0];
    const float* ts     = (const float*)d_in[1];
    const float* planes = (const float*)d_in[2];
    const float* lines  = (const float*)d_in[3];
    const float* params = (const float*)d_in[4];
    const float* W      = (const float*)d_in[5];
    float* out = (float*)d_out;

    // host-side attribute set: not a stream op, graph-capture safe, idempotent
    cudaFuncSetAttribute(k_visnerf,
                         cudaFuncAttributeMaxDynamicSharedMemorySize,
                         SMEM_TOTAL);

    int n = in_sizes[0] / 3;
    int ntiles = (n + TPB - 1) / TPB;
    int nblocks = 1332;                 // ~9 tiles/block at 148 SMs
    if (nblocks > ntiles) nblocks = ntiles;

    k_transpose_planes<<<(3 * RES * RES + 255) / 256, 256>>>(planes);
    k_transpose_lines<<<(3 * RES + 255) / 256, 256>>>(lines);
    k_visnerf<<<nblocks, TPB, SMEM_TOTAL>>>(pts, ts, params, W, out, n);
}